// round 10
// baseline (speedup 1.0000x reference)
#include <cuda_runtime.h>
#include <cuda_bf16.h>
#include <cstdint>
#include <math.h>

#define D 128
#define GEMM_ROWS 64           // rows per tile
#define GEMM_THREADS 256       // 8 warps: 4 row-strips x 2 col-halves
#define PADW 136               // padded row stride in bf16 units (272B, 16B-multiple)
#define GEMM_BLOCKS 296        // persistent: 2 blocks/SM x 148 SMs

// Scratch: Y = z @ W, [100000, 128] fp32 (51.2 MB). Device global => no allocation.
__device__ float g_Y[100000 * 128];

#define LDSM4(r0, r1, r2, r3, addr)                                          \
    asm volatile("ldmatrix.sync.aligned.m8n8.x4.shared.b16 {%0,%1,%2,%3}, [%4];" \
                 : "=r"(r0), "=r"(r1), "=r"(r2), "=r"(r3) : "r"(addr))

// ---------------------------------------------------------------------------
// Kernel 1 (persistent): Y = z @ W via bf16-split MMA (Markidis 3-term),
// ldmatrix fragments. Each block splits W (fp32 -> bf16 hi/lo, transposed)
// into smem ONCE in its prologue, then loops over 64-row z tiles.
// Smem: z hi/lo [64][136], Wt hi/lo [128][136] = 104448 B -> 2 blocks/SM.
// ---------------------------------------------------------------------------
__global__ __launch_bounds__(GEMM_THREADS) void gemm_zW_tc(
    const float* __restrict__ z, const float* __restrict__ W, int N, int n_tiles)
{
    extern __shared__ __nv_bfloat16 sm[];
    __nv_bfloat16* z1 = sm;                               // [64][PADW]
    __nv_bfloat16* z2 = sm + GEMM_ROWS * PADW;
    __nv_bfloat16* w1 = sm + 2 * GEMM_ROWS * PADW;        // [f][d] transposed
    __nv_bfloat16* w2 = sm + 2 * GEMM_ROWS * PADW + 128 * PADW;

    const int tid  = threadIdx.x;
    const int warp = tid >> 5;
    const int lane = tid & 31;
    const int wr   = warp & 3;    // row strip
    const int wc   = warp >> 2;   // col half (0/1)

    // One-time W split: W[d][f] fp32 -> w1[f][d], w2[f][d] bf16 hi/lo
    for (int idx = tid; idx < D * D; idx += GEMM_THREADS) {
        const int d = idx >> 7, f = idx & 127;
        const float v = W[idx];
        const __nv_bfloat16 h = __float2bfloat16(v);
        const __nv_bfloat16 l = __float2bfloat16(v - __bfloat162float(h));
        w1[f * PADW + d] = h;
        w2[f * PADW + d] = l;
    }

    // Shared-space base addresses (bytes)
    const uint32_t base = (uint32_t)__cvta_generic_to_shared(sm);
    const uint32_t z1s = base;
    const uint32_t z2s = base + GEMM_ROWS * PADW * 2;
    const uint32_t w1s = base + 2 * GEMM_ROWS * PADW * 2;
    const uint32_t w2s = w1s + 128 * PADW * 2;

    // A lane address: row = wr*16 + (lane&15), col = (lane>>4)*8 (+k0)
    const uint32_t aoff = (uint32_t)(((wr * 16 + (lane & 15)) * PADW + (lane >> 4) * 8) * 2);
    // B lane address: lane>>3 bit0 -> +8 k, bit1 -> next 8 n-rows (next tt)
    const uint32_t boff = (uint32_t)((((lane & 7) + (lane >> 4) * 8) * PADW + ((lane >> 3) & 1) * 8) * 2);

    const int g   = lane >> 2;
    const int tig = lane & 3;

    for (int tile = blockIdx.x; tile < n_tiles; tile += GEMM_BLOCKS) {
        const int row0 = tile * GEMM_ROWS;

        __syncthreads();   // WAR: previous tile's LDSM reads done; also orders W writes (1st iter)

        // z tile: float4 loads, split, packed bf16x2 stores
        for (int i = tid; i < GEMM_ROWS * 32; i += GEMM_THREADS) {
            const int r = i >> 5, c = (i & 31) * 4;
            const int gr = row0 + r;
            float4 v = make_float4(0.f, 0.f, 0.f, 0.f);
            if (gr < N) v = *(const float4*)(z + (size_t)gr * D + c);

            const __nv_bfloat16 h0 = __float2bfloat16(v.x), h1 = __float2bfloat16(v.y);
            const __nv_bfloat16 h2 = __float2bfloat16(v.z), h3 = __float2bfloat16(v.w);
            const __nv_bfloat16 l0 = __float2bfloat16(v.x - __bfloat162float(h0));
            const __nv_bfloat16 l1 = __float2bfloat16(v.y - __bfloat162float(h1));
            const __nv_bfloat16 l2 = __float2bfloat16(v.z - __bfloat162float(h2));
            const __nv_bfloat16 l3 = __float2bfloat16(v.w - __bfloat162float(h3));

            uint2 hp, lp;
            hp.x = (unsigned)__bfloat16_as_ushort(h0) | ((unsigned)__bfloat16_as_ushort(h1) << 16);
            hp.y = (unsigned)__bfloat16_as_ushort(h2) | ((unsigned)__bfloat16_as_ushort(h3) << 16);
            lp.x = (unsigned)__bfloat16_as_ushort(l0) | ((unsigned)__bfloat16_as_ushort(l1) << 16);
            lp.y = (unsigned)__bfloat16_as_ushort(l2) | ((unsigned)__bfloat16_as_ushort(l3) << 16);
            *(uint2*)(z1 + r * PADW + c) = hp;
            *(uint2*)(z2 + r * PADW + c) = lp;
        }
        __syncthreads();

        float acc[8][4];
        #pragma unroll
        for (int t = 0; t < 8; t++)
            #pragma unroll
            for (int c = 0; c < 4; c++) acc[t][c] = 0.f;

        #pragma unroll
        for (int ks = 0; ks < 8; ks++) {
            const int k0 = ks * 16;
            unsigned ah0, ah1, ah2, ah3, al0, al1, al2, al3;
            LDSM4(ah0, ah1, ah2, ah3, z1s + aoff + k0 * 2);
            LDSM4(al0, al1, al2, al3, z2s + aoff + k0 * 2);

            #pragma unroll
            for (int p = 0; p < 4; p++) {
                const uint32_t nk = (uint32_t)(((wc * 8 + 2 * p) * 8 * PADW + k0) * 2);
                unsigned bh0, bh1, bh2, bh3, bl0, bl1, bl2, bl3;
                LDSM4(bh0, bh1, bh2, bh3, w1s + boff + nk);
                LDSM4(bl0, bl1, bl2, bl3, w2s + boff + nk);

                #pragma unroll
                for (int q = 0; q < 2; q++) {
                    const int tt = 2 * p + q;
                    const unsigned Bh0 = q ? bh2 : bh0, Bh1 = q ? bh3 : bh1;
                    const unsigned Bl0 = q ? bl2 : bl0, Bl1 = q ? bl3 : bl1;
                    asm volatile(
                        "mma.sync.aligned.m16n8k16.row.col.f32.bf16.bf16.f32 "
                        "{%0,%1,%2,%3}, {%4,%5,%6,%7}, {%8,%9}, {%0,%1,%2,%3};\n"
                        : "+f"(acc[tt][0]), "+f"(acc[tt][1]), "+f"(acc[tt][2]), "+f"(acc[tt][3])
                        : "r"(ah0), "r"(ah1), "r"(ah2), "r"(ah3), "r"(Bh0), "r"(Bh1));
                    asm volatile(
                        "mma.sync.aligned.m16n8k16.row.col.f32.bf16.bf16.f32 "
                        "{%0,%1,%2,%3}, {%4,%5,%6,%7}, {%8,%9}, {%0,%1,%2,%3};\n"
                        : "+f"(acc[tt][0]), "+f"(acc[tt][1]), "+f"(acc[tt][2]), "+f"(acc[tt][3])
                        : "r"(ah0), "r"(ah1), "r"(ah2), "r"(ah3), "r"(Bl0), "r"(Bl1));
                    asm volatile(
                        "mma.sync.aligned.m16n8k16.row.col.f32.bf16.bf16.f32 "
                        "{%0,%1,%2,%3}, {%4,%5,%6,%7}, {%8,%9}, {%0,%1,%2,%3};\n"
                        : "+f"(acc[tt][0]), "+f"(acc[tt][1]), "+f"(acc[tt][2]), "+f"(acc[tt][3])
                        : "r"(al0), "r"(al1), "r"(al2), "r"(al3), "r"(Bh0), "r"(Bh1));
                }
            }
        }

        // Store (overlaps next tile's loads; barrier at loop head covers WAR)
        const int gr0 = row0 + wr * 16 + g;
        const int gr1 = gr0 + 8;
        #pragma unroll
        for (int tt = 0; tt < 8; tt++) {
            const int col = (wc * 8 + tt) * 8 + tig * 2;
            if (gr0 < N) *(float2*)(g_Y + (size_t)gr0 * D + col) = make_float2(acc[tt][0], acc[tt][1]);
            if (gr1 < N) *(float2*)(g_Y + (size_t)gr1 * D + col) = make_float2(acc[tt][2], acc[tt][3]);
        }
    }
}

// ---------------------------------------------------------------------------
// Kernel 2: out[e] = sigmoid( dot( Y[edge1[e]], z[edge0[e]] ) )
// 4 edges per warp, 8 lanes per edge, MLP=8 float4 gathers per thread.
// Two passes (blockIdx.y) partitioned by j: per-pass hot set = z (51.2MB) +
// half of Y (25.6MB) = 77MB, fits L2 -> kills capacity-miss churn.
// ---------------------------------------------------------------------------
__global__ __launch_bounds__(256) void edge_decode(
    const float* __restrict__ z, const void* __restrict__ ei_raw,
    float* __restrict__ out, int E, int N)
{
    const int lane  = threadIdx.x & 31;
    const int gwarp = (blockIdx.x * 256 + threadIdx.x) >> 5;
    const int sub   = lane >> 3;
    const int lane8 = lane & 7;
    const int pass  = blockIdx.y;

    const int probe = __ldg((const int*)ei_raw + 2 * lane + 1);
    const bool is64 = (__ballot_sync(0xffffffffu, probe != 0) == 0u);

    const int e_real = gwarp * 4 + sub;
    const int e      = min(e_real, E - 1);

    int i, j;
    if (is64) {
        const long long* ei = (const long long*)ei_raw;
        i = (int)__ldg(ei + e);
        j = (int)__ldg(ei + (size_t)E + e);
    } else {
        const int* ei = (const int*)ei_raw;
        i = __ldg(ei + e);
        j = __ldg(ei + (size_t)E + e);
    }
    i = min(max(i, 0), N - 1);
    j = min(max(j, 0), N - 1);

    const int jhalf = N >> 1;
    const bool active = (e_real < E) && ((j < jhalf) == (pass == 0));

    float s = 0.f;
    if (active) {
        const float4* Yrow = (const float4*)(g_Y + (size_t)j * D);
        const float4* zrow = (const float4*)(z   + (size_t)i * D);

        float4 a[4], b[4];
        #pragma unroll
        for (int k = 0; k < 4; k++) a[k] = __ldg(Yrow + k * 8 + lane8);
        #pragma unroll
        for (int k = 0; k < 4; k++) b[k] = __ldg(zrow + k * 8 + lane8);

        #pragma unroll
        for (int k = 0; k < 4; k++)
            s += a[k].x * b[k].x + a[k].y * b[k].y + a[k].z * b[k].z + a[k].w * b[k].w;
    }

    // All 32 lanes execute the shuffles (full mask); inactive groups carry 0.
    s += __shfl_xor_sync(0xffffffffu, s, 4);
    s += __shfl_xor_sync(0xffffffffu, s, 2);
    s += __shfl_xor_sync(0xffffffffu, s, 1);

    if (active && lane8 == 0) out[e_real] = 1.0f / (1.0f + expf(-s));
}

// ---------------------------------------------------------------------------
extern "C" void kernel_launch(void* const* d_in, const int* in_sizes, int n_in,
                              void* d_out, int out_size)
{
    // Identify inputs by element count (z: N*128 largest, ei: 2*E middle, W: 16384 smallest)
    int idx[3] = {0, 1, 2};
    for (int a = 0; a < 2; a++)
        for (int b = a + 1; b < 3; b++)
            if (in_sizes[idx[b]] > in_sizes[idx[a]]) { int t = idx[a]; idx[a] = idx[b]; idx[b] = t; }
    const int iz = idx[0], ie = idx[1], iw = idx[2];

    const float* z   = (const float*)d_in[iz];
    const void*  ei  = d_in[ie];
    const float* W   = (const float*)d_in[iw];
    float*       out = (float*)d_out;

    const int N = in_sizes[iz] / D;   // 100000
    const int E = in_sizes[ie] / 2;   // 625000

    const int n_tiles = (N + GEMM_ROWS - 1) / GEMM_ROWS;
    const int gemm_smem = (2 * GEMM_ROWS + 2 * 128) * PADW * (int)sizeof(__nv_bfloat16); // 104448
    cudaFuncSetAttribute(gemm_zW_tc, cudaFuncAttributeMaxDynamicSharedMemorySize, gemm_smem);
    gemm_zW_tc<<<GEMM_BLOCKS, GEMM_THREADS, gemm_smem>>>(z, W, N, n_tiles);

    const int edges_per_block = (256 / 32) * 4;   // 32
    const int edge_blocks = (E + edges_per_block - 1) / edges_per_block;
    dim3 egrid(edge_blocks, 2);
    edge_decode<<<egrid, 256>>>(z, ei, out, E, N);
}

// round 12
// speedup vs baseline: 1.2948x; 1.2948x over previous
#include <cuda_runtime.h>
#include <cuda_bf16.h>
#include <cstdint>
#include <math.h>

#define D 128
#define GEMM_ROWS 64           // rows per tile
#define GEMM_THREADS 256       // 8 warps: 4 row-strips x 2 col-halves
#define PADW 136               // padded row stride in bf16 units (272B, 16B-multiple)
#define GEMM_BLOCKS 296        // persistent: 2 blocks/SM x 148 SMs

// Scratch: Y = z @ W, [100000, 128] fp32 (51.2 MB). Device global => no allocation.
__device__ float g_Y[100000 * 128];

#define LDSM4(r0, r1, r2, r3, addr)                                          \
    asm volatile("ldmatrix.sync.aligned.m8n8.x4.shared.b16 {%0,%1,%2,%3}, [%4];" \
                 : "=r"(r0), "=r"(r1), "=r"(r2), "=r"(r3) : "r"(addr))

// ---------------------------------------------------------------------------
// Kernel 1 (persistent): Y = z @ W via bf16-split MMA (Markidis 3-term),
// ldmatrix fragments. Each block splits W (fp32 -> bf16 hi/lo, transposed)
// into smem ONCE in its prologue, then loops over 64-row z tiles.
// Smem: z hi/lo [64][136], Wt hi/lo [128][136] = 104448 B -> 2 blocks/SM.
// ---------------------------------------------------------------------------
__global__ __launch_bounds__(GEMM_THREADS) void gemm_zW_tc(
    const float* __restrict__ z, const float* __restrict__ W, int N, int n_tiles)
{
    extern __shared__ __nv_bfloat16 sm[];
    __nv_bfloat16* z1 = sm;                               // [64][PADW]
    __nv_bfloat16* z2 = sm + GEMM_ROWS * PADW;
    __nv_bfloat16* w1 = sm + 2 * GEMM_ROWS * PADW;        // [f][d] transposed
    __nv_bfloat16* w2 = sm + 2 * GEMM_ROWS * PADW + 128 * PADW;

    const int tid  = threadIdx.x;
    const int warp = tid >> 5;
    const int lane = tid & 31;
    const int wr   = warp & 3;    // row strip
    const int wc   = warp >> 2;   // col half (0/1)

    // One-time W split: W[d][f] fp32 -> w1[f][d], w2[f][d] bf16 hi/lo
    for (int idx = tid; idx < D * D; idx += GEMM_THREADS) {
        const int d = idx >> 7, f = idx & 127;
        const float v = W[idx];
        const __nv_bfloat16 h = __float2bfloat16(v);
        const __nv_bfloat16 l = __float2bfloat16(v - __bfloat162float(h));
        w1[f * PADW + d] = h;
        w2[f * PADW + d] = l;
    }

    // Shared-space base addresses (bytes)
    const uint32_t base = (uint32_t)__cvta_generic_to_shared(sm);
    const uint32_t z1s = base;
    const uint32_t z2s = base + GEMM_ROWS * PADW * 2;
    const uint32_t w1s = base + 2 * GEMM_ROWS * PADW * 2;
    const uint32_t w2s = w1s + 128 * PADW * 2;

    // A lane address: row = wr*16 + (lane&15), col = (lane>>4)*8 (+k0)
    const uint32_t aoff = (uint32_t)(((wr * 16 + (lane & 15)) * PADW + (lane >> 4) * 8) * 2);
    // B lane address: lane>>3 bit0 -> +8 k, bit1 -> next 8 n-rows (next tt)
    const uint32_t boff = (uint32_t)((((lane & 7) + (lane >> 4) * 8) * PADW + ((lane >> 3) & 1) * 8) * 2);

    const int g   = lane >> 2;
    const int tig = lane & 3;

    for (int tile = blockIdx.x; tile < n_tiles; tile += GEMM_BLOCKS) {
        const int row0 = tile * GEMM_ROWS;

        __syncthreads();   // WAR: previous tile's LDSM reads done; also orders W writes (1st iter)

        // z tile: float4 loads, split, packed bf16x2 stores
        for (int i = tid; i < GEMM_ROWS * 32; i += GEMM_THREADS) {
            const int r = i >> 5, c = (i & 31) * 4;
            const int gr = row0 + r;
            float4 v = make_float4(0.f, 0.f, 0.f, 0.f);
            if (gr < N) v = *(const float4*)(z + (size_t)gr * D + c);

            const __nv_bfloat16 h0 = __float2bfloat16(v.x), h1 = __float2bfloat16(v.y);
            const __nv_bfloat16 h2 = __float2bfloat16(v.z), h3 = __float2bfloat16(v.w);
            const __nv_bfloat16 l0 = __float2bfloat16(v.x - __bfloat162float(h0));
            const __nv_bfloat16 l1 = __float2bfloat16(v.y - __bfloat162float(h1));
            const __nv_bfloat16 l2 = __float2bfloat16(v.z - __bfloat162float(h2));
            const __nv_bfloat16 l3 = __float2bfloat16(v.w - __bfloat162float(h3));

            uint2 hp, lp;
            hp.x = (unsigned)__bfloat16_as_ushort(h0) | ((unsigned)__bfloat16_as_ushort(h1) << 16);
            hp.y = (unsigned)__bfloat16_as_ushort(h2) | ((unsigned)__bfloat16_as_ushort(h3) << 16);
            lp.x = (unsigned)__bfloat16_as_ushort(l0) | ((unsigned)__bfloat16_as_ushort(l1) << 16);
            lp.y = (unsigned)__bfloat16_as_ushort(l2) | ((unsigned)__bfloat16_as_ushort(l3) << 16);
            *(uint2*)(z1 + r * PADW + c) = hp;
            *(uint2*)(z2 + r * PADW + c) = lp;
        }
        __syncthreads();

        float acc[8][4];
        #pragma unroll
        for (int t = 0; t < 8; t++)
            #pragma unroll
            for (int c = 0; c < 4; c++) acc[t][c] = 0.f;

        #pragma unroll
        for (int ks = 0; ks < 8; ks++) {
            const int k0 = ks * 16;
            unsigned ah0, ah1, ah2, ah3, al0, al1, al2, al3;
            LDSM4(ah0, ah1, ah2, ah3, z1s + aoff + k0 * 2);
            LDSM4(al0, al1, al2, al3, z2s + aoff + k0 * 2);

            #pragma unroll
            for (int p = 0; p < 4; p++) {
                const uint32_t nk = (uint32_t)(((wc * 8 + 2 * p) * 8 * PADW + k0) * 2);
                unsigned bh0, bh1, bh2, bh3, bl0, bl1, bl2, bl3;
                LDSM4(bh0, bh1, bh2, bh3, w1s + boff + nk);
                LDSM4(bl0, bl1, bl2, bl3, w2s + boff + nk);

                #pragma unroll
                for (int q = 0; q < 2; q++) {
                    const int tt = 2 * p + q;
                    const unsigned Bh0 = q ? bh2 : bh0, Bh1 = q ? bh3 : bh1;
                    const unsigned Bl0 = q ? bl2 : bl0, Bl1 = q ? bl3 : bl1;
                    asm volatile(
                        "mma.sync.aligned.m16n8k16.row.col.f32.bf16.bf16.f32 "
                        "{%0,%1,%2,%3}, {%4,%5,%6,%7}, {%8,%9}, {%0,%1,%2,%3};\n"
                        : "+f"(acc[tt][0]), "+f"(acc[tt][1]), "+f"(acc[tt][2]), "+f"(acc[tt][3])
                        : "r"(ah0), "r"(ah1), "r"(ah2), "r"(ah3), "r"(Bh0), "r"(Bh1));
                    asm volatile(
                        "mma.sync.aligned.m16n8k16.row.col.f32.bf16.bf16.f32 "
                        "{%0,%1,%2,%3}, {%4,%5,%6,%7}, {%8,%9}, {%0,%1,%2,%3};\n"
                        : "+f"(acc[tt][0]), "+f"(acc[tt][1]), "+f"(acc[tt][2]), "+f"(acc[tt][3])
                        : "r"(ah0), "r"(ah1), "r"(ah2), "r"(ah3), "r"(Bl0), "r"(Bl1));
                    asm volatile(
                        "mma.sync.aligned.m16n8k16.row.col.f32.bf16.bf16.f32 "
                        "{%0,%1,%2,%3}, {%4,%5,%6,%7}, {%8,%9}, {%0,%1,%2,%3};\n"
                        : "+f"(acc[tt][0]), "+f"(acc[tt][1]), "+f"(acc[tt][2]), "+f"(acc[tt][3])
                        : "r"(al0), "r"(al1), "r"(al2), "r"(al3), "r"(Bh0), "r"(Bh1));
                }
            }
        }

        // Store (overlaps next tile's loads; barrier at loop head covers WAR)
        const int gr0 = row0 + wr * 16 + g;
        const int gr1 = gr0 + 8;
        #pragma unroll
        for (int tt = 0; tt < 8; tt++) {
            const int col = (wc * 8 + tt) * 8 + tig * 2;
            if (gr0 < N) *(float2*)(g_Y + (size_t)gr0 * D + col) = make_float2(acc[tt][0], acc[tt][1]);
            if (gr1 < N) *(float2*)(g_Y + (size_t)gr1 * D + col) = make_float2(acc[tt][2], acc[tt][3]);
        }
    }
}

// ---------------------------------------------------------------------------
// Kernel 2: out[e] = sigmoid( dot( Y[edge1[e]], z[edge0[e]] ) )
// 4 edges per warp, 8 lanes per edge. Lane element set: {k*64 + lane8*8 + 0..7}
// for k in {0,1}. z read as 2x 32B v8.b32 with L2::evict_last (pins z in L2;
// Y is the churn victim). Y read as 4x float4 at matching offsets.
// ---------------------------------------------------------------------------
__global__ __launch_bounds__(256) void edge_decode(
    const float* __restrict__ z, const void* __restrict__ ei_raw,
    float* __restrict__ out, int E, int N)
{
    const int lane  = threadIdx.x & 31;
    const int gwarp = (blockIdx.x * 256 + threadIdx.x) >> 5;
    const int sub   = lane >> 3;
    const int lane8 = lane & 7;

    const int probe = __ldg((const int*)ei_raw + 2 * lane + 1);
    const bool is64 = (__ballot_sync(0xffffffffu, probe != 0) == 0u);

    const int e_real = gwarp * 4 + sub;
    const int e      = min(e_real, E - 1);

    int i, j;
    if (is64) {
        const long long* ei = (const long long*)ei_raw;
        i = (int)__ldg(ei + e);
        j = (int)__ldg(ei + (size_t)E + e);
    } else {
        const int* ei = (const int*)ei_raw;
        i = __ldg(ei + e);
        j = __ldg(ei + (size_t)E + e);
    }
    i = min(max(i, 0), N - 1);
    j = min(max(j, 0), N - 1);

    const float* Yrow = g_Y + (size_t)j * D;
    const float* zrow = z   + (size_t)i * D;

    // Y: 4 float4 at elem offsets k*64 + lane8*8 + m*4
    float4 a[4];
    #pragma unroll
    for (int k = 0; k < 2; k++)
        #pragma unroll
        for (int m = 0; m < 2; m++)
            a[k * 2 + m] = __ldg((const float4*)(Yrow + k * 64 + lane8 * 8 + m * 4));

    // z: 2 x 256-bit loads with evict_last, elem offsets k*64 + lane8*8
    float b[16];
    #pragma unroll
    for (int k = 0; k < 2; k++) {
        const float* p = zrow + k * 64 + lane8 * 8;
        asm volatile("ld.global.nc.L2::evict_last.v8.b32 {%0,%1,%2,%3,%4,%5,%6,%7}, [%8];"
                     : "=f"(b[k*8+0]), "=f"(b[k*8+1]), "=f"(b[k*8+2]), "=f"(b[k*8+3]),
                       "=f"(b[k*8+4]), "=f"(b[k*8+5]), "=f"(b[k*8+6]), "=f"(b[k*8+7])
                     : "l"(p));
    }

    float s = 0.f;
    #pragma unroll
    for (int k = 0; k < 2; k++)
        #pragma unroll
        for (int m = 0; m < 2; m++) {
            const float4 av = a[k * 2 + m];
            const float* bv = b + k * 8 + m * 4;
            s += av.x * bv[0] + av.y * bv[1] + av.z * bv[2] + av.w * bv[3];
        }

    s += __shfl_xor_sync(0xffffffffu, s, 4);
    s += __shfl_xor_sync(0xffffffffu, s, 2);
    s += __shfl_xor_sync(0xffffffffu, s, 1);

    if (lane8 == 0 && e_real < E) out[e_real] = 1.0f / (1.0f + expf(-s));
}

// ---------------------------------------------------------------------------
extern "C" void kernel_launch(void* const* d_in, const int* in_sizes, int n_in,
                              void* d_out, int out_size)
{
    // Identify inputs by element count (z: N*128 largest, ei: 2*E middle, W: 16384 smallest)
    int idx[3] = {0, 1, 2};
    for (int a = 0; a < 2; a++)
        for (int b = a + 1; b < 3; b++)
            if (in_sizes[idx[b]] > in_sizes[idx[a]]) { int t = idx[a]; idx[a] = idx[b]; idx[b] = t; }
    const int iz = idx[0], ie = idx[1], iw = idx[2];

    const float* z   = (const float*)d_in[iz];
    const void*  ei  = d_in[ie];
    const float* W   = (const float*)d_in[iw];
    float*       out = (float*)d_out;

    const int N = in_sizes[iz] / D;   // 100000
    const int E = in_sizes[ie] / 2;   // 625000

    const int n_tiles = (N + GEMM_ROWS - 1) / GEMM_ROWS;
    const int gemm_smem = (2 * GEMM_ROWS + 2 * 128) * PADW * (int)sizeof(__nv_bfloat16); // 104448
    cudaFuncSetAttribute(gemm_zW_tc, cudaFuncAttributeMaxDynamicSharedMemorySize, gemm_smem);
    gemm_zW_tc<<<GEMM_BLOCKS, GEMM_THREADS, gemm_smem>>>(z, W, N, n_tiles);

    const int edges_per_block = (256 / 32) * 4;   // 32
    const int edge_blocks = (E + edges_per_block - 1) / edges_per_block;
    edge_decode<<<edge_blocks, 256>>>(z, ei, out, E, N);
}

// round 13
// speedup vs baseline: 1.3184x; 1.0182x over previous
#include <cuda_runtime.h>
#include <cuda_bf16.h>
#include <cstdint>
#include <math.h>

#define D 128
#define GEMM_ROWS 64           // rows per tile
#define GEMM_THREADS 256       // 8 warps: 4 row-strips x 2 col-halves
#define PADW 136               // padded row stride in bf16 units (272B, 16B-multiple)
#define GEMM_BLOCKS 296        // persistent: 2 blocks/SM x 148 SMs

// Scratch (device globals => no allocation):
__device__ float g_Y[100000 * 128];                 // Y = z @ W, fp32
__device__ __nv_bfloat16 g_w1t[128 * 128];          // hi(W) transposed: [f][d]
__device__ __nv_bfloat16 g_w2t[128 * 128];          // lo(W) transposed

#define LDSM4(r0, r1, r2, r3, addr)                                          \
    asm volatile("ldmatrix.sync.aligned.m8n8.x4.shared.b16 {%0,%1,%2,%3}, [%4];" \
                 : "=r"(r0), "=r"(r1), "=r"(r2), "=r"(r3) : "r"(addr))

// ---------------------------------------------------------------------------
// Pre-split W: W[d][f] fp32 -> g_w1t[f][d], g_w2t[f][d] bf16 hi/lo.
// ---------------------------------------------------------------------------
__global__ void split_W(const float* __restrict__ W)
{
    const int idx = blockIdx.x * blockDim.x + threadIdx.x;
    if (idx < D * D) {
        const int d = idx >> 7, f = idx & 127;
        const float v = W[idx];
        const __nv_bfloat16 h = __float2bfloat16(v);
        const __nv_bfloat16 l = __float2bfloat16(v - __bfloat162float(h));
        g_w1t[f * D + d] = h;
        g_w2t[f * D + d] = l;
    }
}

// ---------------------------------------------------------------------------
// Kernel 1 (persistent): Y = z @ W via bf16-split MMA (Markidis 3-term),
// ldmatrix fragments, register double-buffered z loads: each thread issues
// its NEXT tile's 8x LDG.128 before the current tile's MMA phase, hiding
// DRAM latency behind compute.
// Smem: z hi/lo [64][136], Wt hi/lo [128][136] = 104448 B -> 2 blocks/SM.
// ---------------------------------------------------------------------------
__global__ __launch_bounds__(GEMM_THREADS) void gemm_zW_tc(
    const float* __restrict__ z, int N, int n_tiles)
{
    extern __shared__ __nv_bfloat16 sm[];
    __nv_bfloat16* z1 = sm;                               // [64][PADW]
    __nv_bfloat16* z2 = sm + GEMM_ROWS * PADW;
    __nv_bfloat16* w1 = sm + 2 * GEMM_ROWS * PADW;        // [f][d] transposed
    __nv_bfloat16* w2 = sm + 2 * GEMM_ROWS * PADW + 128 * PADW;

    const int tid  = threadIdx.x;
    const int warp = tid >> 5;
    const int lane = tid & 31;
    const int wr   = warp & 3;    // row strip
    const int wc   = warp >> 2;   // col half (0/1)

    // W: one-time vectorized copy of pre-split bf16 (uint4 = 8 bf16)
    {
        const uint4* s1 = (const uint4*)g_w1t;
        const uint4* s2 = (const uint4*)g_w2t;
        for (int i = tid; i < 128 * 16; i += GEMM_THREADS) {
            const int f = i >> 4, c8 = (i & 15) * 8;
            *(uint4*)(w1 + f * PADW + c8) = s1[i];
            *(uint4*)(w2 + f * PADW + c8) = s2[i];
        }
    }

    // Shared-space base addresses (bytes)
    const uint32_t base = (uint32_t)__cvta_generic_to_shared(sm);
    const uint32_t z1s = base;
    const uint32_t z2s = base + GEMM_ROWS * PADW * 2;
    const uint32_t w1s = base + 2 * GEMM_ROWS * PADW * 2;
    const uint32_t w2s = w1s + 128 * PADW * 2;

    // A lane address: row = wr*16 + (lane&15), col = (lane>>4)*8 (+k0)
    const uint32_t aoff = (uint32_t)(((wr * 16 + (lane & 15)) * PADW + (lane >> 4) * 8) * 2);
    // B lane address: lane>>3 bit0 -> +8 k, bit1 -> next 8 n-rows (next tt)
    const uint32_t boff = (uint32_t)((((lane & 7) + (lane >> 4) * 8) * PADW + ((lane >> 3) & 1) * 8) * 2);

    const int g   = lane >> 2;
    const int tig = lane & 3;

    // Per-thread z-load slots: k=0..7, i = tid + k*256, r = i>>5, c = (i&31)*4
    float4 v[8];

    // Prefetch first tile
    {
        const int row0 = blockIdx.x * GEMM_ROWS;
        #pragma unroll
        for (int k = 0; k < 8; k++) {
            const int i = tid + k * GEMM_THREADS;
            const int gr = row0 + (i >> 5);
            v[k] = (gr < N) ? *(const float4*)(z + (size_t)gr * D + (i & 31) * 4)
                            : make_float4(0.f, 0.f, 0.f, 0.f);
        }
    }

    for (int tile = blockIdx.x; tile < n_tiles; tile += GEMM_BLOCKS) {
        __syncthreads();   // WAR: previous tile's LDSM reads done; also orders W copy (1st iter)

        // Convert prefetched regs -> smem (split hi/lo)
        #pragma unroll
        for (int k = 0; k < 8; k++) {
            const int i = tid + k * GEMM_THREADS;
            const int r = i >> 5, c = (i & 31) * 4;
            const float4 vv = v[k];

            const __nv_bfloat16 h0 = __float2bfloat16(vv.x), h1 = __float2bfloat16(vv.y);
            const __nv_bfloat16 h2 = __float2bfloat16(vv.z), h3 = __float2bfloat16(vv.w);
            const __nv_bfloat16 l0 = __float2bfloat16(vv.x - __bfloat162float(h0));
            const __nv_bfloat16 l1 = __float2bfloat16(vv.y - __bfloat162float(h1));
            const __nv_bfloat16 l2 = __float2bfloat16(vv.z - __bfloat162float(h2));
            const __nv_bfloat16 l3 = __float2bfloat16(vv.w - __bfloat162float(h3));

            uint2 hp, lp;
            hp.x = (unsigned)__bfloat16_as_ushort(h0) | ((unsigned)__bfloat16_as_ushort(h1) << 16);
            hp.y = (unsigned)__bfloat16_as_ushort(h2) | ((unsigned)__bfloat16_as_ushort(h3) << 16);
            lp.x = (unsigned)__bfloat16_as_ushort(l0) | ((unsigned)__bfloat16_as_ushort(l1) << 16);
            lp.y = (unsigned)__bfloat16_as_ushort(l2) | ((unsigned)__bfloat16_as_ushort(l3) << 16);
            *(uint2*)(z1 + r * PADW + c) = hp;
            *(uint2*)(z2 + r * PADW + c) = lp;
        }

        // Issue NEXT tile's global loads (independent; overlap with MMA below)
        const int ntile = tile + GEMM_BLOCKS;
        if (ntile < n_tiles) {
            const int nrow0 = ntile * GEMM_ROWS;
            #pragma unroll
            for (int k = 0; k < 8; k++) {
                const int i = tid + k * GEMM_THREADS;
                const int gr = nrow0 + (i >> 5);
                v[k] = (gr < N) ? *(const float4*)(z + (size_t)gr * D + (i & 31) * 4)
                                : make_float4(0.f, 0.f, 0.f, 0.f);
            }
        }

        __syncthreads();   // z tile in smem ready

        float acc[8][4];
        #pragma unroll
        for (int t = 0; t < 8; t++)
            #pragma unroll
            for (int c = 0; c < 4; c++) acc[t][c] = 0.f;

        #pragma unroll
        for (int ks = 0; ks < 8; ks++) {
            const int k0 = ks * 16;
            unsigned ah0, ah1, ah2, ah3, al0, al1, al2, al3;
            LDSM4(ah0, ah1, ah2, ah3, z1s + aoff + k0 * 2);
            LDSM4(al0, al1, al2, al3, z2s + aoff + k0 * 2);

            #pragma unroll
            for (int p = 0; p < 4; p++) {
                const uint32_t nk = (uint32_t)(((wc * 8 + 2 * p) * 8 * PADW + k0) * 2);
                unsigned bh0, bh1, bh2, bh3, bl0, bl1, bl2, bl3;
                LDSM4(bh0, bh1, bh2, bh3, w1s + boff + nk);
                LDSM4(bl0, bl1, bl2, bl3, w2s + boff + nk);

                #pragma unroll
                for (int q = 0; q < 2; q++) {
                    const int tt = 2 * p + q;
                    const unsigned Bh0 = q ? bh2 : bh0, Bh1 = q ? bh3 : bh1;
                    const unsigned Bl0 = q ? bl2 : bl0, Bl1 = q ? bl3 : bl1;
                    asm volatile(
                        "mma.sync.aligned.m16n8k16.row.col.f32.bf16.bf16.f32 "
                        "{%0,%1,%2,%3}, {%4,%5,%6,%7}, {%8,%9}, {%0,%1,%2,%3};\n"
                        : "+f"(acc[tt][0]), "+f"(acc[tt][1]), "+f"(acc[tt][2]), "+f"(acc[tt][3])
                        : "r"(ah0), "r"(ah1), "r"(ah2), "r"(ah3), "r"(Bh0), "r"(Bh1));
                    asm volatile(
                        "mma.sync.aligned.m16n8k16.row.col.f32.bf16.bf16.f32 "
                        "{%0,%1,%2,%3}, {%4,%5,%6,%7}, {%8,%9}, {%0,%1,%2,%3};\n"
                        : "+f"(acc[tt][0]), "+f"(acc[tt][1]), "+f"(acc[tt][2]), "+f"(acc[tt][3])
                        : "r"(ah0), "r"(ah1), "r"(ah2), "r"(ah3), "r"(Bl0), "r"(Bl1));
                    asm volatile(
                        "mma.sync.aligned.m16n8k16.row.col.f32.bf16.bf16.f32 "
                        "{%0,%1,%2,%3}, {%4,%5,%6,%7}, {%8,%9}, {%0,%1,%2,%3};\n"
                        : "+f"(acc[tt][0]), "+f"(acc[tt][1]), "+f"(acc[tt][2]), "+f"(acc[tt][3])
                        : "r"(al0), "r"(al1), "r"(al2), "r"(al3), "r"(Bh0), "r"(Bh1));
                }
            }
        }

        // Store Y
        const int row0 = tile * GEMM_ROWS;
        const int gr0 = row0 + wr * 16 + g;
        const int gr1 = gr0 + 8;
        #pragma unroll
        for (int tt = 0; tt < 8; tt++) {
            const int col = (wc * 8 + tt) * 8 + tig * 2;
            if (gr0 < N) *(float2*)(g_Y + (size_t)gr0 * D + col) = make_float2(acc[tt][0], acc[tt][1]);
            if (gr1 < N) *(float2*)(g_Y + (size_t)gr1 * D + col) = make_float2(acc[tt][2], acc[tt][3]);
        }
    }
}

// ---------------------------------------------------------------------------
// Kernel 2 (R9 form): out[e] = sigmoid( dot( Y[edge1[e]], z[edge0[e]] ) )
// 4 edges per warp, 8 lanes per edge, MLP=8 float4 gathers per thread.
// ---------------------------------------------------------------------------
__global__ __launch_bounds__(256) void edge_decode(
    const float* __restrict__ z, const void* __restrict__ ei_raw,
    float* __restrict__ out, int E, int N)
{
    const int lane  = threadIdx.x & 31;
    const int gwarp = (blockIdx.x * 256 + threadIdx.x) >> 5;
    const int sub   = lane >> 3;
    const int lane8 = lane & 7;

    const int probe = __ldg((const int*)ei_raw + 2 * lane + 1);
    const bool is64 = (__ballot_sync(0xffffffffu, probe != 0) == 0u);

    const int e_real = gwarp * 4 + sub;
    const int e      = min(e_real, E - 1);

    int i, j;
    if (is64) {
        const long long* ei = (const long long*)ei_raw;
        i = (int)__ldg(ei + e);
        j = (int)__ldg(ei + (size_t)E + e);
    } else {
        const int* ei = (const int*)ei_raw;
        i = __ldg(ei + e);
        j = __ldg(ei + (size_t)E + e);
    }
    i = min(max(i, 0), N - 1);
    j = min(max(j, 0), N - 1);

    const float4* Yrow = (const float4*)(g_Y + (size_t)j * D);
    const float4* zrow = (const float4*)(z   + (size_t)i * D);

    float4 a[4], b[4];
    #pragma unroll
    for (int k = 0; k < 4; k++) a[k] = __ldg(Yrow + k * 8 + lane8);
    #pragma unroll
    for (int k = 0; k < 4; k++) b[k] = __ldg(zrow + k * 8 + lane8);

    float s = 0.f;
    #pragma unroll
    for (int k = 0; k < 4; k++)
        s += a[k].x * b[k].x + a[k].y * b[k].y + a[k].z * b[k].z + a[k].w * b[k].w;

    s += __shfl_xor_sync(0xffffffffu, s, 4);
    s += __shfl_xor_sync(0xffffffffu, s, 2);
    s += __shfl_xor_sync(0xffffffffu, s, 1);

    if (lane8 == 0 && e_real < E) out[e_real] = 1.0f / (1.0f + expf(-s));
}

// ---------------------------------------------------------------------------
extern "C" void kernel_launch(void* const* d_in, const int* in_sizes, int n_in,
                              void* d_out, int out_size)
{
    // Identify inputs by element count (z: N*128 largest, ei: 2*E middle, W: 16384 smallest)
    int idx[3] = {0, 1, 2};
    for (int a = 0; a < 2; a++)
        for (int b = a + 1; b < 3; b++)
            if (in_sizes[idx[b]] > in_sizes[idx[a]]) { int t = idx[a]; idx[a] = idx[b]; idx[b] = t; }
    const int iz = idx[0], ie = idx[1], iw = idx[2];

    const float* z   = (const float*)d_in[iz];
    const void*  ei  = d_in[ie];
    const float* W   = (const float*)d_in[iw];
    float*       out = (float*)d_out;

    const int N = in_sizes[iz] / D;   // 100000
    const int E = in_sizes[ie] / 2;   // 625000

    split_W<<<(D * D + 255) / 256, 256>>>(W);

    const int n_tiles = (N + GEMM_ROWS - 1) / GEMM_ROWS;
    const int gemm_smem = (2 * GEMM_ROWS + 2 * 128) * PADW * (int)sizeof(__nv_bfloat16); // 104448
    cudaFuncSetAttribute(gemm_zW_tc, cudaFuncAttributeMaxDynamicSharedMemorySize, gemm_smem);
    gemm_zW_tc<<<GEMM_BLOCKS, GEMM_THREADS, gemm_smem>>>(z, N, n_tiles);

    const int edges_per_block = (256 / 32) * 4;   // 32
    const int edge_blocks = (E + edges_per_block - 1) / edges_per_block;
    edge_decode<<<edge_blocks, 256>>>(z, ei, out, E, N);
}

// round 14
// speedup vs baseline: 1.3269x; 1.0065x over previous
#include <cuda_runtime.h>
#include <cuda_bf16.h>
#include <cstdint>
#include <math.h>

#define D 128
#define GEMM_ROWS 64           // rows per tile
#define GEMM_THREADS 256       // 8 warps: 4 row-strips x 2 col-halves
#define PADW 136               // padded row stride in bf16 units (272B, 16B-multiple)
#define GEMM_BLOCKS 296        // persistent: 2 blocks/SM x 148 SMs

// Scratch: Y = z @ W, [100000, 128] fp32 (51.2 MB). Device global => no allocation.
__device__ float g_Y[100000 * 128];

#define LDSM4(r0, r1, r2, r3, addr)                                          \
    asm volatile("ldmatrix.sync.aligned.m8n8.x4.shared.b16 {%0,%1,%2,%3}, [%4];" \
                 : "=r"(r0), "=r"(r1), "=r"(r2), "=r"(r3) : "r"(addr))

#define LDSM4T(r0, r1, r2, r3, addr)                                         \
    asm volatile("ldmatrix.sync.aligned.m8n8.x4.trans.shared.b16 {%0,%1,%2,%3}, [%4];" \
                 : "=r"(r0), "=r"(r1), "=r"(r2), "=r"(r3) : "r"(addr))

// ---------------------------------------------------------------------------
// Kernel 1 (persistent): Y = z @ W via bf16-split MMA (Markidis 3-term).
// W kept in NATURAL [d=k][f=n] layout in smem (no transpose on fill);
// B-fragments fetched with ldmatrix.trans. A-fragments non-trans as before.
// Smem: z hi/lo [64][136], W hi/lo [128][136] = 104448 B -> 2 blocks/SM.
// ---------------------------------------------------------------------------
__global__ __launch_bounds__(GEMM_THREADS, 2) void gemm_zW_tc(
    const float* __restrict__ z, const float* __restrict__ W, int N, int n_tiles)
{
    extern __shared__ __nv_bfloat16 sm[];
    __nv_bfloat16* z1 = sm;                               // [64][PADW]
    __nv_bfloat16* z2 = sm + GEMM_ROWS * PADW;
    __nv_bfloat16* w1 = sm + 2 * GEMM_ROWS * PADW;        // [d][f] natural
    __nv_bfloat16* w2 = sm + 2 * GEMM_ROWS * PADW + 128 * PADW;

    const int tid  = threadIdx.x;
    const int warp = tid >> 5;
    const int lane = tid & 31;
    const int wr   = warp & 3;    // row strip
    const int wc   = warp >> 2;   // col half (0/1)

    // One-time W fill: natural layout, vectorized (float4 load, uint2 stores)
    for (int i = tid; i < 128 * 32; i += GEMM_THREADS) {
        const int d = i >> 5, c = (i & 31) * 4;
        const float4 v = *(const float4*)(W + d * D + c);

        const __nv_bfloat16 h0 = __float2bfloat16(v.x), h1 = __float2bfloat16(v.y);
        const __nv_bfloat16 h2 = __float2bfloat16(v.z), h3 = __float2bfloat16(v.w);
        const __nv_bfloat16 l0 = __float2bfloat16(v.x - __bfloat162float(h0));
        const __nv_bfloat16 l1 = __float2bfloat16(v.y - __bfloat162float(h1));
        const __nv_bfloat16 l2 = __float2bfloat16(v.z - __bfloat162float(h2));
        const __nv_bfloat16 l3 = __float2bfloat16(v.w - __bfloat162float(h3));

        uint2 hp, lp;
        hp.x = (unsigned)__bfloat16_as_ushort(h0) | ((unsigned)__bfloat16_as_ushort(h1) << 16);
        hp.y = (unsigned)__bfloat16_as_ushort(h2) | ((unsigned)__bfloat16_as_ushort(h3) << 16);
        lp.x = (unsigned)__bfloat16_as_ushort(l0) | ((unsigned)__bfloat16_as_ushort(l1) << 16);
        lp.y = (unsigned)__bfloat16_as_ushort(l2) | ((unsigned)__bfloat16_as_ushort(l3) << 16);
        *(uint2*)(w1 + d * PADW + c) = hp;
        *(uint2*)(w2 + d * PADW + c) = lp;
    }

    // Shared-space base addresses (bytes)
    const uint32_t base = (uint32_t)__cvta_generic_to_shared(sm);
    const uint32_t z1s = base;
    const uint32_t z2s = base + GEMM_ROWS * PADW * 2;
    const uint32_t w1s = base + 2 * GEMM_ROWS * PADW * 2;
    const uint32_t w2s = w1s + 128 * PADW * 2;

    // A lane address: row = wr*16 + (lane&15), col = (lane>>4)*8 (+k0)
    const uint32_t aoff = (uint32_t)(((wr * 16 + (lane & 15)) * PADW + (lane >> 4) * 8) * 2);
    // B (trans) lane address in [k][n] layout:
    //   row k = k0 + (lane&7) + ((lane>>3)&1)*8 ; col n = n0 + (lane>>4)*8
    const uint32_t boff = (uint32_t)((((lane & 7) + ((lane >> 3) & 1) * 8) * PADW + (lane >> 4) * 8) * 2);

    const int g   = lane >> 2;
    const int tig = lane & 3;

    for (int tile = blockIdx.x; tile < n_tiles; tile += GEMM_BLOCKS) {
        const int row0 = tile * GEMM_ROWS;

        __syncthreads();   // WAR: previous tile's LDSM reads done; orders W fill (1st iter)

        // z tile: float4 loads, split, packed bf16x2 stores
        for (int i = tid; i < GEMM_ROWS * 32; i += GEMM_THREADS) {
            const int r = i >> 5, c = (i & 31) * 4;
            const int gr = row0 + r;
            float4 v = make_float4(0.f, 0.f, 0.f, 0.f);
            if (gr < N) v = *(const float4*)(z + (size_t)gr * D + c);

            const __nv_bfloat16 h0 = __float2bfloat16(v.x), h1 = __float2bfloat16(v.y);
            const __nv_bfloat16 h2 = __float2bfloat16(v.z), h3 = __float2bfloat16(v.w);
            const __nv_bfloat16 l0 = __float2bfloat16(v.x - __bfloat162float(h0));
            const __nv_bfloat16 l1 = __float2bfloat16(v.y - __bfloat162float(h1));
            const __nv_bfloat16 l2 = __float2bfloat16(v.z - __bfloat162float(h2));
            const __nv_bfloat16 l3 = __float2bfloat16(v.w - __bfloat162float(h3));

            uint2 hp, lp;
            hp.x = (unsigned)__bfloat16_as_ushort(h0) | ((unsigned)__bfloat16_as_ushort(h1) << 16);
            hp.y = (unsigned)__bfloat16_as_ushort(h2) | ((unsigned)__bfloat16_as_ushort(h3) << 16);
            lp.x = (unsigned)__bfloat16_as_ushort(l0) | ((unsigned)__bfloat16_as_ushort(l1) << 16);
            lp.y = (unsigned)__bfloat16_as_ushort(l2) | ((unsigned)__bfloat16_as_ushort(l3) << 16);
            *(uint2*)(z1 + r * PADW + c) = hp;
            *(uint2*)(z2 + r * PADW + c) = lp;
        }
        __syncthreads();

        float acc[8][4];
        #pragma unroll
        for (int t = 0; t < 8; t++)
            #pragma unroll
            for (int c = 0; c < 4; c++) acc[t][c] = 0.f;

        #pragma unroll
        for (int ks = 0; ks < 8; ks++) {
            const int k0 = ks * 16;
            unsigned ah0, ah1, ah2, ah3, al0, al1, al2, al3;
            LDSM4(ah0, ah1, ah2, ah3, z1s + aoff + k0 * 2);
            LDSM4(al0, al1, al2, al3, z2s + aoff + k0 * 2);

            #pragma unroll
            for (int p = 0; p < 4; p++) {
                const int n0 = (wc * 8 + 2 * p) * 8;
                const uint32_t nk = (uint32_t)((k0 * PADW + n0) * 2);
                unsigned bh0, bh1, bh2, bh3, bl0, bl1, bl2, bl3;
                LDSM4T(bh0, bh1, bh2, bh3, w1s + boff + nk);
                LDSM4T(bl0, bl1, bl2, bl3, w2s + boff + nk);

                #pragma unroll
                for (int q = 0; q < 2; q++) {
                    const int tt = 2 * p + q;
                    const unsigned Bh0 = q ? bh2 : bh0, Bh1 = q ? bh3 : bh1;
                    const unsigned Bl0 = q ? bl2 : bl0, Bl1 = q ? bl3 : bl1;
                    asm volatile(
                        "mma.sync.aligned.m16n8k16.row.col.f32.bf16.bf16.f32 "
                        "{%0,%1,%2,%3}, {%4,%5,%6,%7}, {%8,%9}, {%0,%1,%2,%3};\n"
                        : "+f"(acc[tt][0]), "+f"(acc[tt][1]), "+f"(acc[tt][2]), "+f"(acc[tt][3])
                        : "r"(ah0), "r"(ah1), "r"(ah2), "r"(ah3), "r"(Bh0), "r"(Bh1));
                    asm volatile(
                        "mma.sync.aligned.m16n8k16.row.col.f32.bf16.bf16.f32 "
                        "{%0,%1,%2,%3}, {%4,%5,%6,%7}, {%8,%9}, {%0,%1,%2,%3};\n"
                        : "+f"(acc[tt][0]), "+f"(acc[tt][1]), "+f"(acc[tt][2]), "+f"(acc[tt][3])
                        : "r"(ah0), "r"(ah1), "r"(ah2), "r"(ah3), "r"(Bl0), "r"(Bl1));
                    asm volatile(
                        "mma.sync.aligned.m16n8k16.row.col.f32.bf16.bf16.f32 "
                        "{%0,%1,%2,%3}, {%4,%5,%6,%7}, {%8,%9}, {%0,%1,%2,%3};\n"
                        : "+f"(acc[tt][0]), "+f"(acc[tt][1]), "+f"(acc[tt][2]), "+f"(acc[tt][3])
                        : "r"(al0), "r"(al1), "r"(al2), "r"(al3), "r"(Bh0), "r"(Bh1));
                }
            }
        }

        // Store Y
        const int gr0 = row0 + wr * 16 + g;
        const int gr1 = gr0 + 8;
        #pragma unroll
        for (int tt = 0; tt < 8; tt++) {
            const int col = (wc * 8 + tt) * 8 + tig * 2;
            if (gr0 < N) *(float2*)(g_Y + (size_t)gr0 * D + col) = make_float2(acc[tt][0], acc[tt][1]);
            if (gr1 < N) *(float2*)(g_Y + (size_t)gr1 * D + col) = make_float2(acc[tt][2], acc[tt][3]);
        }
    }
}

// ---------------------------------------------------------------------------
// Kernel 2 (R9 form): out[e] = sigmoid( dot( Y[edge1[e]], z[edge0[e]] ) )
// 4 edges per warp, 8 lanes per edge, MLP=8 float4 gathers per thread.
// ---------------------------------------------------------------------------
__global__ __launch_bounds__(256) void edge_decode(
    const float* __restrict__ z, const void* __restrict__ ei_raw,
    float* __restrict__ out, int E, int N)
{
    const int lane  = threadIdx.x & 31;
    const int gwarp = (blockIdx.x * 256 + threadIdx.x) >> 5;
    const int sub   = lane >> 3;
    const int lane8 = lane & 7;

    const int probe = __ldg((const int*)ei_raw + 2 * lane + 1);
    const bool is64 = (__ballot_sync(0xffffffffu, probe != 0) == 0u);

    const int e_real = gwarp * 4 + sub;
    const int e      = min(e_real, E - 1);

    int i, j;
    if (is64) {
        const long long* ei = (const long long*)ei_raw;
        i = (int)__ldg(ei + e);
        j = (int)__ldg(ei + (size_t)E + e);
    } else {
        const int* ei = (const int*)ei_raw;
        i = __ldg(ei + e);
        j = __ldg(ei + (size_t)E + e);
    }
    i = min(max(i, 0), N - 1);
    j = min(max(j, 0), N - 1);

    const float4* Yrow = (const float4*)(g_Y + (size_t)j * D);
    const float4* zrow = (const float4*)(z   + (size_t)i * D);

    float4 a[4], b[4];
    #pragma unroll
    for (int k = 0; k < 4; k++) a[k] = __ldg(Yrow + k * 8 + lane8);
    #pragma unroll
    for (int k = 0; k < 4; k++) b[k] = __ldg(zrow + k * 8 + lane8);

    float s = 0.f;
    #pragma unroll
    for (int k = 0; k < 4; k++)
        s += a[k].x * b[k].x + a[k].y * b[k].y + a[k].z * b[k].z + a[k].w * b[k].w;

    s += __shfl_xor_sync(0xffffffffu, s, 4);
    s += __shfl_xor_sync(0xffffffffu, s, 2);
    s += __shfl_xor_sync(0xffffffffu, s, 1);

    if (lane8 == 0 && e_real < E) out[e_real] = 1.0f / (1.0f + expf(-s));
}

// ---------------------------------------------------------------------------
extern "C" void kernel_launch(void* const* d_in, const int* in_sizes, int n_in,
                              void* d_out, int out_size)
{
    // Identify inputs by element count (z: N*128 largest, ei: 2*E middle, W: 16384 smallest)
    int idx[3] = {0, 1, 2};
    for (int a = 0; a < 2; a++)
        for (int b = a + 1; b < 3; b++)
            if (in_sizes[idx[b]] > in_sizes[idx[a]]) { int t = idx[a]; idx[a] = idx[b]; idx[b] = t; }
    const int iz = idx[0], ie = idx[1], iw = idx[2];

    const float* z   = (const float*)d_in[iz];
    const void*  ei  = d_in[ie];
    const float* W   = (const float*)d_in[iw];
    float*       out = (float*)d_out;

    const int N = in_sizes[iz] / D;   // 100000
    const int E = in_sizes[ie] / 2;   // 625000

    const int n_tiles = (N + GEMM_ROWS - 1) / GEMM_ROWS;
    const int gemm_smem = (2 * GEMM_ROWS + 2 * 128) * PADW * (int)sizeof(__nv_bfloat16); // 104448
    cudaFuncSetAttribute(gemm_zW_tc, cudaFuncAttributeMaxDynamicSharedMemorySize, gemm_smem);
    gemm_zW_tc<<<GEMM_BLOCKS, GEMM_THREADS, gemm_smem>>>(z, W, N, n_tiles);

    const int edges_per_block = (256 / 32) * 4;   // 32
    const int edge_blocks = (E + edges_per_block - 1) / edges_per_block;
    edge_decode<<<edge_blocks, 256>>>(z, ei, out, E, N);
}

// round 16
// speedup vs baseline: 1.3583x; 1.0237x over previous
#include <cuda_runtime.h>
#include <cuda_bf16.h>
#include <cstdint>
#include <math.h>

#define D 128
#define GEMM_ROWS 64           // rows per tile
#define GEMM_THREADS 256       // 8 warps: 4 row-strips x 2 col-halves
#define PADW 136               // padded row stride in bf16 units (272B, 16B-multiple)
#define GEMM_BLOCKS 296        // persistent: 2 blocks/SM x 148 SMs

// Scratch: Y = z @ W, [100000, 128] fp32 (51.2 MB). Device global => no allocation.
__device__ float g_Y[100000 * 128];

#define LDSM4(r0, r1, r2, r3, addr)                                          \
    asm volatile("ldmatrix.sync.aligned.m8n8.x4.shared.b16 {%0,%1,%2,%3}, [%4];" \
                 : "=r"(r0), "=r"(r1), "=r"(r2), "=r"(r3) : "r"(addr))

// ---------------------------------------------------------------------------
// Kernel 1 (persistent): Y = z @ W via bf16-split MMA (Markidis 3-term),
// ldmatrix fragments — R9 mainloop, byte-identical. Prologue fuses the W
// split in TWO HALVES: stage 64 W-rows fp32 in the z1/z2 region (32768 B
// <= 34816 B), transpose-split into w1/w2 [f][d] (disjoint bytes), repeat.
// Smem: z hi/lo [64][136], Wt hi/lo [128][136] = 104448 B -> 2 blocks/SM.
// ---------------------------------------------------------------------------
__global__ __launch_bounds__(GEMM_THREADS) void gemm_zW_tc(
    const float* __restrict__ z, const float* __restrict__ W, int N, int n_tiles)
{
    extern __shared__ __nv_bfloat16 sm[];
    __nv_bfloat16* z1 = sm;                               // [64][PADW] (17408 B)
    __nv_bfloat16* z2 = sm + GEMM_ROWS * PADW;            // (17408 B)
    __nv_bfloat16* w1 = sm + 2 * GEMM_ROWS * PADW;        // [f][d] transposed
    __nv_bfloat16* w2 = sm + 2 * GEMM_ROWS * PADW + 128 * PADW;

    const int tid  = threadIdx.x;
    const int warp = tid >> 5;
    const int lane = tid & 31;
    const int wr   = warp & 3;    // row strip
    const int wc   = warp >> 2;   // col half (0/1)

    // ---- One-time W transpose-split via smem staging, two 64-row halves ----
    {
        float* stage = (float*)sm;    // 32768 B per half; fits z1/z2 (34816 B)
        #pragma unroll
        for (int half = 0; half < 2; half++) {
            // coalesced fp32 load of W rows [half*64, half*64+64)
            for (int i = tid; i < 2048; i += GEMM_THREADS)
                *(float4*)(stage + i * 4) = *(const float4*)(W + half * 64 * D + i * 4);
            __syncthreads();
            // transpose-split: f = tid>>1 (0..127), 32 d's per thread
            const int f   = tid >> 1;
            const int dq  = (tid & 1) * 32;     // d_local base within this half
            #pragma unroll
            for (int kk = 0; kk < 8; kk++) {
                const int dl = dq + kk * 4;     // local d (0..63)
                unsigned hp[2], lp[2];
                #pragma unroll
                for (int m = 0; m < 2; m++) {
                    const float va = stage[(dl + 2 * m + 0) * D + f];
                    const float vb = stage[(dl + 2 * m + 1) * D + f];
                    const __nv_bfloat16 ha = __float2bfloat16(va);
                    const __nv_bfloat16 hb = __float2bfloat16(vb);
                    const __nv_bfloat16 la = __float2bfloat16(va - __bfloat162float(ha));
                    const __nv_bfloat16 lb = __float2bfloat16(vb - __bfloat162float(hb));
                    hp[m] = (unsigned)__bfloat16_as_ushort(ha) | ((unsigned)__bfloat16_as_ushort(hb) << 16);
                    lp[m] = (unsigned)__bfloat16_as_ushort(la) | ((unsigned)__bfloat16_as_ushort(lb) << 16);
                }
                const int d = half * 64 + dl;   // global d
                *(uint2*)(w1 + f * PADW + d) = make_uint2(hp[0], hp[1]);
                *(uint2*)(w2 + f * PADW + d) = make_uint2(lp[0], lp[1]);
            }
            __syncthreads();   // stage consumed before next half overwrites it
        }
    }

    // Shared-space base addresses (bytes)
    const uint32_t base = (uint32_t)__cvta_generic_to_shared(sm);
    const uint32_t z1s = base;
    const uint32_t z2s = base + GEMM_ROWS * PADW * 2;
    const uint32_t w1s = base + 2 * GEMM_ROWS * PADW * 2;
    const uint32_t w2s = w1s + 128 * PADW * 2;

    // A lane address: row = wr*16 + (lane&15), col = (lane>>4)*8 (+k0)
    const uint32_t aoff = (uint32_t)(((wr * 16 + (lane & 15)) * PADW + (lane >> 4) * 8) * 2);
    // B lane address: lane>>3 bit0 -> +8 k, bit1 -> next 8 n-rows (next tt)
    const uint32_t boff = (uint32_t)((((lane & 7) + (lane >> 4) * 8) * PADW + ((lane >> 3) & 1) * 8) * 2);

    const int g   = lane >> 2;
    const int tig = lane & 3;

    for (int tile = blockIdx.x; tile < n_tiles; tile += GEMM_BLOCKS) {
        const int row0 = tile * GEMM_ROWS;

        __syncthreads();   // WAR: previous tile's LDSM reads done before z overwrite

        // z tile: float4 loads, split, packed bf16x2 stores
        for (int i = tid; i < GEMM_ROWS * 32; i += GEMM_THREADS) {
            const int r = i >> 5, c = (i & 31) * 4;
            const int gr = row0 + r;
            float4 v = make_float4(0.f, 0.f, 0.f, 0.f);
            if (gr < N) v = *(const float4*)(z + (size_t)gr * D + c);

            const __nv_bfloat16 h0 = __float2bfloat16(v.x), h1 = __float2bfloat16(v.y);
            const __nv_bfloat16 h2 = __float2bfloat16(v.z), h3 = __float2bfloat16(v.w);
            const __nv_bfloat16 l0 = __float2bfloat16(v.x - __bfloat162float(h0));
            const __nv_bfloat16 l1 = __float2bfloat16(v.y - __bfloat162float(h1));
            const __nv_bfloat16 l2 = __float2bfloat16(v.z - __bfloat162float(h2));
            const __nv_bfloat16 l3 = __float2bfloat16(v.w - __bfloat162float(h3));

            uint2 hp, lp;
            hp.x = (unsigned)__bfloat16_as_ushort(h0) | ((unsigned)__bfloat16_as_ushort(h1) << 16);
            hp.y = (unsigned)__bfloat16_as_ushort(h2) | ((unsigned)__bfloat16_as_ushort(h3) << 16);
            lp.x = (unsigned)__bfloat16_as_ushort(l0) | ((unsigned)__bfloat16_as_ushort(l1) << 16);
            lp.y = (unsigned)__bfloat16_as_ushort(l2) | ((unsigned)__bfloat16_as_ushort(l3) << 16);
            *(uint2*)(z1 + r * PADW + c) = hp;
            *(uint2*)(z2 + r * PADW + c) = lp;
        }
        __syncthreads();

        float acc[8][4];
        #pragma unroll
        for (int t = 0; t < 8; t++)
            #pragma unroll
            for (int c = 0; c < 4; c++) acc[t][c] = 0.f;

        #pragma unroll
        for (int ks = 0; ks < 8; ks++) {
            const int k0 = ks * 16;
            unsigned ah0, ah1, ah2, ah3, al0, al1, al2, al3;
            LDSM4(ah0, ah1, ah2, ah3, z1s + aoff + k0 * 2);
            LDSM4(al0, al1, al2, al3, z2s + aoff + k0 * 2);

            #pragma unroll
            for (int p = 0; p < 4; p++) {
                const uint32_t nk = (uint32_t)(((wc * 8 + 2 * p) * 8 * PADW + k0) * 2);
                unsigned bh0, bh1, bh2, bh3, bl0, bl1, bl2, bl3;
                LDSM4(bh0, bh1, bh2, bh3, w1s + boff + nk);
                LDSM4(bl0, bl1, bl2, bl3, w2s + boff + nk);

                #pragma unroll
                for (int q = 0; q < 2; q++) {
                    const int tt = 2 * p + q;
                    const unsigned Bh0 = q ? bh2 : bh0, Bh1 = q ? bh3 : bh1;
                    const unsigned Bl0 = q ? bl2 : bl0, Bl1 = q ? bl3 : bl1;
                    asm volatile(
                        "mma.sync.aligned.m16n8k16.row.col.f32.bf16.bf16.f32 "
                        "{%0,%1,%2,%3}, {%4,%5,%6,%7}, {%8,%9}, {%0,%1,%2,%3};\n"
                        : "+f"(acc[tt][0]), "+f"(acc[tt][1]), "+f"(acc[tt][2]), "+f"(acc[tt][3])
                        : "r"(ah0), "r"(ah1), "r"(ah2), "r"(ah3), "r"(Bh0), "r"(Bh1));
                    asm volatile(
                        "mma.sync.aligned.m16n8k16.row.col.f32.bf16.bf16.f32 "
                        "{%0,%1,%2,%3}, {%4,%5,%6,%7}, {%8,%9}, {%0,%1,%2,%3};\n"
                        : "+f"(acc[tt][0]), "+f"(acc[tt][1]), "+f"(acc[tt][2]), "+f"(acc[tt][3])
                        : "r"(ah0), "r"(ah1), "r"(ah2), "r"(ah3), "r"(Bl0), "r"(Bl1));
                    asm volatile(
                        "mma.sync.aligned.m16n8k16.row.col.f32.bf16.bf16.f32 "
                        "{%0,%1,%2,%3}, {%4,%5,%6,%7}, {%8,%9}, {%0,%1,%2,%3};\n"
                        : "+f"(acc[tt][0]), "+f"(acc[tt][1]), "+f"(acc[tt][2]), "+f"(acc[tt][3])
                        : "r"(al0), "r"(al1), "r"(al2), "r"(al3), "r"(Bh0), "r"(Bh1));
                }
            }
        }

        // Store Y
        const int gr0 = row0 + wr * 16 + g;
        const int gr1 = gr0 + 8;
        #pragma unroll
        for (int tt = 0; tt < 8; tt++) {
            const int col = (wc * 8 + tt) * 8 + tig * 2;
            if (gr0 < N) *(float2*)(g_Y + (size_t)gr0 * D + col) = make_float2(acc[tt][0], acc[tt][1]);
            if (gr1 < N) *(float2*)(g_Y + (size_t)gr1 * D + col) = make_float2(acc[tt][2], acc[tt][3]);
        }
    }
}

// ---------------------------------------------------------------------------
// Kernel 2 (R9 form): out[e] = sigmoid( dot( Y[edge1[e]], z[edge0[e]] ) )
// 4 edges per warp, 8 lanes per edge, MLP=8 float4 gathers per thread.
// ---------------------------------------------------------------------------
__global__ __launch_bounds__(256) void edge_decode(
    const float* __restrict__ z, const void* __restrict__ ei_raw,
    float* __restrict__ out, int E, int N)
{
    const int lane  = threadIdx.x & 31;
    const int gwarp = (blockIdx.x * 256 + threadIdx.x) >> 5;
    const int sub   = lane >> 3;
    const int lane8 = lane & 7;

    const int probe = __ldg((const int*)ei_raw + 2 * lane + 1);
    const bool is64 = (__ballot_sync(0xffffffffu, probe != 0) == 0u);

    const int e_real = gwarp * 4 + sub;
    const int e      = min(e_real, E - 1);

    int i, j;
    if (is64) {
        const long long* ei = (const long long*)ei_raw;
        i = (int)__ldg(ei + e);
        j = (int)__ldg(ei + (size_t)E + e);
    } else {
        const int* ei = (const int*)ei_raw;
        i = __ldg(ei + e);
        j = __ldg(ei + (size_t)E + e);
    }
    i = min(max(i, 0), N - 1);
    j = min(max(j, 0), N - 1);

    const float4* Yrow = (const float4*)(g_Y + (size_t)j * D);
    const float4* zrow = (const float4*)(z   + (size_t)i * D);

    float4 a[4], b[4];
    #pragma unroll
    for (int k = 0; k < 4; k++) a[k] = __ldg(Yrow + k * 8 + lane8);
    #pragma unroll
    for (int k = 0; k < 4; k++) b[k] = __ldg(zrow + k * 8 + lane8);

    float s = 0.f;
    #pragma unroll
    for (int k = 0; k < 4; k++)
        s += a[k].x * b[k].x + a[k].y * b[k].y + a[k].z * b[k].z + a[k].w * b[k].w;

    s += __shfl_xor_sync(0xffffffffu, s, 4);
    s += __shfl_xor_sync(0xffffffffu, s, 2);
    s += __shfl_xor_sync(0xffffffffu, s, 1);

    if (lane8 == 0 && e_real < E) out[e_real] = 1.0f / (1.0f + expf(-s));
}

// ---------------------------------------------------------------------------
extern "C" void kernel_launch(void* const* d_in, const int* in_sizes, int n_in,
                              void* d_out, int out_size)
{
    // Identify inputs by element count (z: N*128 largest, ei: 2*E middle, W: 16384 smallest)
    int idx[3] = {0, 1, 2};
    for (int a = 0; a < 2; a++)
        for (int b = a + 1; b < 3; b++)
            if (in_sizes[idx[b]] > in_sizes[idx[a]]) { int t = idx[a]; idx[a] = idx[b]; idx[b] = t; }
    const int iz = idx[0], ie = idx[1], iw = idx[2];

    const float* z   = (const float*)d_in[iz];
    const void*  ei  = d_in[ie];
    const float* W   = (const float*)d_in[iw];
    float*       out = (float*)d_out;

    const int N = in_sizes[iz] / D;   // 100000
    const int E = in_sizes[ie] / 2;   // 625000

    const int n_tiles = (N + GEMM_ROWS - 1) / GEMM_ROWS;
    const int gemm_smem = (2 * GEMM_ROWS + 2 * 128) * PADW * (int)sizeof(__nv_bfloat16); // 104448
    cudaFuncSetAttribute(gemm_zW_tc, cudaFuncAttributeMaxDynamicSharedMemorySize, gemm_smem);
    gemm_zW_tc<<<GEMM_BLOCKS, GEMM_THREADS, gemm_smem>>>(z, W, N, n_tiles);

    const int edges_per_block = (256 / 32) * 4;   // 32
    const int edge_blocks = (E + edges_per_block - 1) / edges_per_block;
    edge_decode<<<edge_blocks, 256>>>(z, ei, out, E, N);
}

// round 17
// speedup vs baseline: 1.4876x; 1.0952x over previous
#include <cuda_runtime.h>
#include <cuda_fp16.h>
#include <cstdint>
#include <math.h>

#define D 128
#define GEMM_ROWS 64           // rows per tile
#define GEMM_THREADS 256       // 8 warps: 4 row-strips x 2 col-halves
#define PADW 136               // padded row stride in fp16 units (272B, 16B-multiple)
#define GEMM_BLOCKS 296        // persistent: 2 blocks/SM x 148 SMs

// Scratch: Y = z @ W, [100000, 128] fp32 (51.2 MB). Device global => no allocation.
__device__ float g_Y[100000 * 128];

#define LDSM4(r0, r1, r2, r3, addr)                                          \
    asm volatile("ldmatrix.sync.aligned.m8n8.x4.shared.b16 {%0,%1,%2,%3}, [%4];" \
                 : "=r"(r0), "=r"(r1), "=r"(r2), "=r"(r3) : "r"(addr))

// ---------------------------------------------------------------------------
// Kernel 1 (persistent): Y = z @ W via fp16 2-term split MMA:
//   A = ah + al (fp16 hi + fp16 residual, exact to 2^-24); B = fp16(W) once.
//   D = ah*bh + al*bh; only error is a*(b - bh) ~ 2^-12 -> rel_err ~1e-4.
// Prologue fuses the W transpose-round in two staged halves.
// Smem: z hi/lo [64][136] + Wt [128][136] fp16 = 69632 B -> 2+ blocks/SM.
// ---------------------------------------------------------------------------
__global__ __launch_bounds__(GEMM_THREADS) void gemm_zW_tc(
    const float* __restrict__ z, const float* __restrict__ W, int N, int n_tiles)
{
    extern __shared__ __half sm[];
    __half* z1 = sm;                               // [64][PADW] (17408 B)
    __half* z2 = sm + GEMM_ROWS * PADW;            // (17408 B)
    __half* w  = sm + 2 * GEMM_ROWS * PADW;        // [f][d] transposed (34816 B)

    const int tid  = threadIdx.x;
    const int warp = tid >> 5;
    const int lane = tid & 31;
    const int wr   = warp & 3;    // row strip
    const int wc   = warp >> 2;   // col half (0/1)

    // ---- One-time W transpose-round via smem staging, two 64-row halves ----
    {
        float* stage = (float*)sm;    // 32768 B per half; fits z1/z2 (34816 B)
        #pragma unroll
        for (int half = 0; half < 2; half++) {
            for (int i = tid; i < 2048; i += GEMM_THREADS)
                *(float4*)(stage + i * 4) = *(const float4*)(W + half * 64 * D + i * 4);
            __syncthreads();
            const int f  = tid >> 1;
            const int dq = (tid & 1) * 32;
            #pragma unroll
            for (int kk = 0; kk < 8; kk++) {
                const int dl = dq + kk * 4;
                unsigned hp[2];
                #pragma unroll
                for (int m = 0; m < 2; m++) {
                    const __half ha = __float2half(stage[(dl + 2 * m + 0) * D + f]);
                    const __half hb = __float2half(stage[(dl + 2 * m + 1) * D + f]);
                    hp[m] = (unsigned)__half_as_ushort(ha) | ((unsigned)__half_as_ushort(hb) << 16);
                }
                const int d = half * 64 + dl;
                *(uint2*)(w + f * PADW + d) = make_uint2(hp[0], hp[1]);
            }
            __syncthreads();
        }
    }

    // Shared-space base addresses (bytes)
    const uint32_t base = (uint32_t)__cvta_generic_to_shared(sm);
    const uint32_t z1s = base;
    const uint32_t z2s = base + GEMM_ROWS * PADW * 2;
    const uint32_t ws  = base + 2 * GEMM_ROWS * PADW * 2;

    // A lane address: row = wr*16 + (lane&15), col = (lane>>4)*8 (+k0)
    const uint32_t aoff = (uint32_t)(((wr * 16 + (lane & 15)) * PADW + (lane >> 4) * 8) * 2);
    // B lane address: lane>>3 bit0 -> +8 k, bit1 -> next 8 n-rows (next tt)
    const uint32_t boff = (uint32_t)((((lane & 7) + (lane >> 4) * 8) * PADW + ((lane >> 3) & 1) * 8) * 2);

    const int g   = lane >> 2;
    const int tig = lane & 3;

    for (int tile = blockIdx.x; tile < n_tiles; tile += GEMM_BLOCKS) {
        const int row0 = tile * GEMM_ROWS;

        __syncthreads();   // WAR: previous tile's LDSM reads done before z overwrite

        // z tile: float4 loads, fp16 hi/lo split, packed stores
        for (int i = tid; i < GEMM_ROWS * 32; i += GEMM_THREADS) {
            const int r = i >> 5, c = (i & 31) * 4;
            const int gr = row0 + r;
            float4 v = make_float4(0.f, 0.f, 0.f, 0.f);
            if (gr < N) v = *(const float4*)(z + (size_t)gr * D + c);

            const __half h0 = __float2half(v.x), h1 = __float2half(v.y);
            const __half h2 = __float2half(v.z), h3 = __float2half(v.w);
            const __half l0 = __float2half(v.x - __half2float(h0));
            const __half l1 = __float2half(v.y - __half2float(h1));
            const __half l2 = __float2half(v.z - __half2float(h2));
            const __half l3 = __float2half(v.w - __half2float(h3));

            uint2 hp, lp;
            hp.x = (unsigned)__half_as_ushort(h0) | ((unsigned)__half_as_ushort(h1) << 16);
            hp.y = (unsigned)__half_as_ushort(h2) | ((unsigned)__half_as_ushort(h3) << 16);
            lp.x = (unsigned)__half_as_ushort(l0) | ((unsigned)__half_as_ushort(l1) << 16);
            lp.y = (unsigned)__half_as_ushort(l2) | ((unsigned)__half_as_ushort(l3) << 16);
            *(uint2*)(z1 + r * PADW + c) = hp;
            *(uint2*)(z2 + r * PADW + c) = lp;
        }
        __syncthreads();

        float acc[8][4];
        #pragma unroll
        for (int t = 0; t < 8; t++)
            #pragma unroll
            for (int c = 0; c < 4; c++) acc[t][c] = 0.f;

        #pragma unroll
        for (int ks = 0; ks < 8; ks++) {
            const int k0 = ks * 16;
            unsigned ah0, ah1, ah2, ah3, al0, al1, al2, al3;
            LDSM4(ah0, ah1, ah2, ah3, z1s + aoff + k0 * 2);
            LDSM4(al0, al1, al2, al3, z2s + aoff + k0 * 2);

            #pragma unroll
            for (int p = 0; p < 4; p++) {
                const uint32_t nk = (uint32_t)(((wc * 8 + 2 * p) * 8 * PADW + k0) * 2);
                unsigned bh0, bh1, bh2, bh3;
                LDSM4(bh0, bh1, bh2, bh3, ws + boff + nk);

                #pragma unroll
                for (int q = 0; q < 2; q++) {
                    const int tt = 2 * p + q;
                    const unsigned Bh0 = q ? bh2 : bh0, Bh1 = q ? bh3 : bh1;
                    asm volatile(
                        "mma.sync.aligned.m16n8k16.row.col.f32.f16.f16.f32 "
                        "{%0,%1,%2,%3}, {%4,%5,%6,%7}, {%8,%9}, {%0,%1,%2,%3};\n"
                        : "+f"(acc[tt][0]), "+f"(acc[tt][1]), "+f"(acc[tt][2]), "+f"(acc[tt][3])
                        : "r"(ah0), "r"(ah1), "r"(ah2), "r"(ah3), "r"(Bh0), "r"(Bh1));
                    asm volatile(
                        "mma.sync.aligned.m16n8k16.row.col.f32.f16.f16.f32 "
                        "{%0,%1,%2,%3}, {%4,%5,%6,%7}, {%8,%9}, {%0,%1,%2,%3};\n"
                        : "+f"(acc[tt][0]), "+f"(acc[tt][1]), "+f"(acc[tt][2]), "+f"(acc[tt][3])
                        : "r"(al0), "r"(al1), "r"(al2), "r"(al3), "r"(Bh0), "r"(Bh1));
                }
            }
        }

        // Store Y
        const int gr0 = row0 + wr * 16 + g;
        const int gr1 = gr0 + 8;
        #pragma unroll
        for (int tt = 0; tt < 8; tt++) {
            const int col = (wc * 8 + tt) * 8 + tig * 2;
            if (gr0 < N) *(float2*)(g_Y + (size_t)gr0 * D + col) = make_float2(acc[tt][0], acc[tt][1]);
            if (gr1 < N) *(float2*)(g_Y + (size_t)gr1 * D + col) = make_float2(acc[tt][2], acc[tt][3]);
        }
    }
}

// ---------------------------------------------------------------------------
// Kernel 2 (R9 form): out[e] = sigmoid( dot( Y[edge1[e]], z[edge0[e]] ) )
// 4 edges per warp, 8 lanes per edge, MLP=8 float4 gathers per thread.
// ---------------------------------------------------------------------------
__global__ __launch_bounds__(256) void edge_decode(
    const float* __restrict__ z, const void* __restrict__ ei_raw,
    float* __restrict__ out, int E, int N)
{
    const int lane  = threadIdx.x & 31;
    const int gwarp = (blockIdx.x * 256 + threadIdx.x) >> 5;
    const int sub   = lane >> 3;
    const int lane8 = lane & 7;

    const int probe = __ldg((const int*)ei_raw + 2 * lane + 1);
    const bool is64 = (__ballot_sync(0xffffffffu, probe != 0) == 0u);

    const int e_real = gwarp * 4 + sub;
    const int e      = min(e_real, E - 1);

    int i, j;
    if (is64) {
        const long long* ei = (const long long*)ei_raw;
        i = (int)__ldg(ei + e);
        j = (int)__ldg(ei + (size_t)E + e);
    } else {
        const int* ei = (const int*)ei_raw;
        i = __ldg(ei + e);
        j = __ldg(ei + (size_t)E + e);
    }
    i = min(max(i, 0), N - 1);
    j = min(max(j, 0), N - 1);

    const float4* Yrow = (const float4*)(g_Y + (size_t)j * D);
    const float4* zrow = (const float4*)(z   + (size_t)i * D);

    float4 a[4], b[4];
    #pragma unroll
    for (int k = 0; k < 4; k++) a[k] = __ldg(Yrow + k * 8 + lane8);
    #pragma unroll
    for (int k = 0; k < 4; k++) b[k] = __ldg(zrow + k * 8 + lane8);

    float s = 0.f;
    #pragma unroll
    for (int k = 0; k < 4; k++)
        s += a[k].x * b[k].x + a[k].y * b[k].y + a[k].z * b[k].z + a[k].w * b[k].w;

    s += __shfl_xor_sync(0xffffffffu, s, 4);
    s += __shfl_xor_sync(0xffffffffu, s, 2);
    s += __shfl_xor_sync(0xffffffffu, s, 1);

    if (lane8 == 0 && e_real < E) out[e_real] = 1.0f / (1.0f + expf(-s));
}

// ---------------------------------------------------------------------------
extern "C" void kernel_launch(void* const* d_in, const int* in_sizes, int n_in,
                              void* d_out, int out_size)
{
    // Identify inputs by element count (z: N*128 largest, ei: 2*E middle, W: 16384 smallest)
    int idx[3] = {0, 1, 2};
    for (int a = 0; a < 2; a++)
        for (int b = a + 1; b < 3; b++)
            if (in_sizes[idx[b]] > in_sizes[idx[a]]) { int t = idx[a]; idx[a] = idx[b]; idx[b] = t; }
    const int iz = idx[0], ie = idx[1], iw = idx[2];

    const float* z   = (const float*)d_in[iz];
    const void*  ei  = d_in[ie];
    const float* W   = (const float*)d_in[iw];
    float*       out = (float*)d_out;

    const int N = in_sizes[iz] / D;   // 100000
    const int E = in_sizes[ie] / 2;   // 625000

    const int n_tiles = (N + GEMM_ROWS - 1) / GEMM_ROWS;
    const int gemm_smem = (2 * GEMM_ROWS + 128) * PADW * (int)sizeof(__half); // 69632
    cudaFuncSetAttribute(gemm_zW_tc, cudaFuncAttributeMaxDynamicSharedMemorySize, gemm_smem);
    gemm_zW_tc<<<GEMM_BLOCKS, GEMM_THREADS, gemm_smem>>>(z, W, N, n_tiles);

    const int edges_per_block = (256 / 32) * 4;   // 32
    const int edge_blocks = (E + edges_per_block - 1) / edges_per_block;
    edge_decode<<<edge_blocks, 256>>>(z, ei, out, E, N);
}